// round 5
// baseline (speedup 1.0000x reference)
#include <cuda_runtime.h>
#include <math.h>

// ---------------------------------------------------------------------------
// DGCNN forward, CSR-gather with pre-scaled features.
//   xws[v] = (h@W) * dinv[v]  =>  gcn_out[d] = dinv[d]*(sum_e ew*xws[src] + xws[d])
// z-embedding GEMM folded into a 1000-row table; head FC split into a batched
// GEMM kernel so Wl1 is read ~100x, not 1000x.
// ---------------------------------------------------------------------------

#define NN 100000
#define EE 1600000
#define NG 1000
#define SLOT 64   // padded CSR row stride (Poisson(16) tail beyond 64 ~1e-20)

__device__ int   g_cnt[NN];
__device__ float g_dinv[NN];
__device__ int2  g_adj[(size_t)NN * SLOT];   // (src, ew bits)
__device__ float g_zw[1000 * 32];            // z_emb @ Wg1 table
__device__ float g_xwA[NN * 32];             // pre-scaled features
__device__ float g_xwB[NN * 32];
__device__ float g_h1[NN * 32];              // tanh outputs per layer (coalesced)
__device__ float g_h2[NN * 32];
__device__ float g_h3[NN * 32];
__device__ float g_xw4[NN];
__device__ float g_y2[NG * 352];             // head intermediate (352 = 32*11)

// ---- CSR build --------------------------------------------------------------

__global__ void k_zero(int n) {
    int i = blockIdx.x * blockDim.x + threadIdx.x;
    if (i < n) g_cnt[i] = 0;
}

__global__ void k_fill(const int* __restrict__ src, const int* __restrict__ dst,
                       const float* __restrict__ ew, int e) {
    int i = blockIdx.x * blockDim.x + threadIdx.x;
    if (i >= e) return;
    int d = dst[i];
    int pos = atomicAdd(&g_cnt[d], 1);
    if (pos < SLOT) g_adj[(size_t)d * SLOT + pos] = make_int2(src[i], __float_as_int(ew[i]));
}

// warp per node: deg = 1 + sum(row ew); dinv = rsqrt(deg); pad row to mult of 8.
__global__ void k_degdinv(int n) {
    int tid  = blockIdx.x * blockDim.x + threadIdx.x;
    int node = tid >> 5, lane = tid & 31;
    if (node >= n) return;
    int c = min(g_cnt[node], SLOT);
    int2* row = g_adj + (size_t)node * SLOT;
    float w = 0.f;
    if (lane < c)      w += __int_as_float(row[lane].y);
    if (lane + 32 < c) w += __int_as_float(row[lane + 32].y);
#pragma unroll
    for (int off = 16; off; off >>= 1) w += __shfl_xor_sync(0xffffffffu, w, off);
    int cpad = (c + 7) & ~7;
    if (c + lane < cpad) row[c + lane] = make_int2(0, 0);   // zero-weight dummy
    if (lane == 0) {
        g_dinv[node] = rsqrtf(1.0f + w);
        g_cnt[node]  = cpad;
    }
}

// ---- z table: zw = z_emb @ Wg1 (1000 x 32) ---------------------------------

__global__ void k_zw(const float* __restrict__ z_emb, const float* __restrict__ W, int nz) {
    __shared__ float sW[1024];
    int tid = threadIdx.x;
    for (int i = tid; i < 1024; i += 256) sW[i] = W[i];
    __syncthreads();
    int warp = tid >> 5, lane = tid & 31;
    int row = blockIdx.x * 8 + warp;
    if (row >= nz) return;
    float h = z_emb[row * 32 + lane];
    float o = 0.f;
#pragma unroll
    for (int k = 0; k < 32; k++)
        o = fmaf(__shfl_sync(0xffffffffu, h, k), sW[k * 32 + lane], o);
    g_zw[row * 32 + lane] = o;
}

// xwA[node] = zw[z[node]] * dinv[node]  (pure gather)
__global__ void k_emb_gather(const int* __restrict__ z, int n) {
    int i = blockIdx.x * blockDim.x + threadIdx.x;
    if (i >= n * 32) return;
    int node = i >> 5;
    g_xwA[i] = g_zw[z[node] * 32 + (i & 31)] * g_dinv[node];
}

// ---- aggregation: acc = sum ew*xws[src] + xws[self], 8 edges in flight ------

__device__ __forceinline__ float agg8(const float* __restrict__ xwIn,
                                      int node, int lane, int c) {
    float acc = xwIn[node * 32 + lane];
    const int4* row4 = (const int4*)(g_adj + (size_t)node * SLOT);
    for (int j = 0; j < c; j += 8) {
        int4 m0 = row4[(j >> 1) + 0];
        int4 m1 = row4[(j >> 1) + 1];
        int4 m2 = row4[(j >> 1) + 2];
        int4 m3 = row4[(j >> 1) + 3];
        float v0 = xwIn[m0.x * 32 + lane];
        float v1 = xwIn[m0.z * 32 + lane];
        float v2 = xwIn[m1.x * 32 + lane];
        float v3 = xwIn[m1.z * 32 + lane];
        float v4 = xwIn[m2.x * 32 + lane];
        float v5 = xwIn[m2.z * 32 + lane];
        float v6 = xwIn[m3.x * 32 + lane];
        float v7 = xwIn[m3.z * 32 + lane];
        acc = fmaf(__int_as_float(m0.y), v0, acc);
        acc = fmaf(__int_as_float(m0.w), v1, acc);
        acc = fmaf(__int_as_float(m1.y), v2, acc);
        acc = fmaf(__int_as_float(m1.w), v3, acc);
        acc = fmaf(__int_as_float(m2.y), v4, acc);
        acc = fmaf(__int_as_float(m2.w), v5, acc);
        acc = fmaf(__int_as_float(m3.y), v6, acc);
        acc = fmaf(__int_as_float(m3.w), v7, acc);
    }
    return acc;
}

// ---- fused GCN layer: agg -> tanh -> h buffer -> GEMM (4 accums) -> prescale

__global__ void __launch_bounds__(256)
k_layer32(const float* __restrict__ bprev, const float* __restrict__ W,
          float* __restrict__ hOut, const float* __restrict__ xwIn,
          float* __restrict__ xwOut, int n) {
    __shared__ float sW[1024];
    int tid = threadIdx.x;
    for (int i = tid; i < 1024; i += 256) sW[i] = W[i];
    __syncthreads();
    int warp = tid >> 5, lane = tid & 31;
    int node = blockIdx.x * 8 + warp;
    if (node >= n) return;
    float dv = g_dinv[node];
    int   c  = g_cnt[node];
    float acc = agg8(xwIn, node, lane, c);
    float h = tanhf(fmaf(acc, dv, bprev[lane]));
    hOut[node * 32 + lane] = h;
    float o0 = 0.f, o1 = 0.f, o2 = 0.f, o3 = 0.f;
#pragma unroll
    for (int k = 0; k < 32; k += 4) {
        o0 = fmaf(__shfl_sync(0xffffffffu, h, k + 0), sW[(k + 0) * 32 + lane], o0);
        o1 = fmaf(__shfl_sync(0xffffffffu, h, k + 1), sW[(k + 1) * 32 + lane], o1);
        o2 = fmaf(__shfl_sync(0xffffffffu, h, k + 2), sW[(k + 2) * 32 + lane], o2);
        o3 = fmaf(__shfl_sync(0xffffffffu, h, k + 3), sW[(k + 3) * 32 + lane], o3);
    }
    xwOut[node * 32 + lane] = ((o0 + o1) + (o2 + o3)) * dv;
}

// last GCN layer: project to scalar via Wg4 (pre-scaled output)
__global__ void __launch_bounds__(256)
k_layer_last(const float* __restrict__ bg3, const float* __restrict__ Wg4,
             const float* __restrict__ xwIn, int n) {
    int tid = blockIdx.x * blockDim.x + threadIdx.x;
    int node = tid >> 5, lane = tid & 31;
    if (node >= n) return;
    float dv = g_dinv[node];
    int   c  = g_cnt[node];
    float acc = agg8(xwIn, node, lane, c);
    float h = tanhf(fmaf(acc, dv, bg3[lane]));
    g_h3[node * 32 + lane] = h;
    float p = h * Wg4[lane];
#pragma unroll
    for (int off = 16; off; off >>= 1) p += __shfl_down_sync(0xffffffffu, p, off);
    if (lane == 0) g_xw4[node] = p * dv;
}

// ---- head part 1: scalar agg + sort-pool + conv1 + pool + conv2 -> g_y2 -----

__global__ void __launch_bounds__(128)
k_head1(const float* __restrict__ bg4,
        const float* __restrict__ Wc1, const float* __restrict__ bc1,
        const float* __restrict__ Wc2, const float* __restrict__ bc2) {
    __shared__ float v[100];
    __shared__ int   topidx[30];
    __shared__ float top[30 * 97];
    __shared__ float y1[16 * 30];
    __shared__ float pmax[16 * 15];

    int g = blockIdx.x;
    int t = threadIdx.x;
    float b4 = bg4[0];

    // layer-4 scalar aggregation, thread per node (rows padded, mult of 8)
    if (t < 100) {
        int node = g * 100 + t;
        float acc = g_xw4[node];
        int c = g_cnt[node];
        const int4* row4 = (const int4*)(g_adj + (size_t)node * SLOT);
        for (int j = 0; j < c; j += 8) {
            int4 m0 = row4[(j >> 1) + 0];
            int4 m1 = row4[(j >> 1) + 1];
            int4 m2 = row4[(j >> 1) + 2];
            int4 m3 = row4[(j >> 1) + 3];
            float v0 = g_xw4[m0.x], v1 = g_xw4[m0.z];
            float v2 = g_xw4[m1.x], v3 = g_xw4[m1.z];
            float v4 = g_xw4[m2.x], v5 = g_xw4[m2.z];
            float v6 = g_xw4[m3.x], v7 = g_xw4[m3.z];
            acc = fmaf(__int_as_float(m0.y), v0, acc);
            acc = fmaf(__int_as_float(m0.w), v1, acc);
            acc = fmaf(__int_as_float(m1.y), v2, acc);
            acc = fmaf(__int_as_float(m1.w), v3, acc);
            acc = fmaf(__int_as_float(m2.y), v4, acc);
            acc = fmaf(__int_as_float(m2.w), v5, acc);
            acc = fmaf(__int_as_float(m3.y), v6, acc);
            acc = fmaf(__int_as_float(m3.w), v7, acc);
        }
        v[t] = tanhf(fmaf(acc, g_dinv[node], b4));
    }
    __syncthreads();

    // stable descending rank select (ties -> lower index first)
    if (t < 100) {
        float vt = v[t];
        int r = 0;
#pragma unroll 4
        for (int m = 0; m < 100; m++) {
            float vm = v[m];
            r += (vm > vt) || (vm == vt && m < t);
        }
        if (r < 30) topidx[r] = t;
    }
    __syncthreads();

    // gather top-30 latent rows (h1|h2|h3|v) into [30][97]
    for (int e = t; e < 30 * 97; e += 128) {
        int r = e / 97, d = e - 97 * r;
        int nd = g * 100 + topidx[r];
        float val;
        if (d < 32)       val = g_h1[nd * 32 + d];
        else if (d < 64)  val = g_h2[nd * 32 + d - 32];
        else if (d < 96)  val = g_h3[nd * 32 + d - 64];
        else              val = v[topidx[r]];
        top[e] = val;
    }
    __syncthreads();

    // Conv1d(1,16,97,stride 97)
    for (int o = t; o < 16 * 30; o += 128) {
        int c = o / 30, k = o - 30 * c;
        const float* w  = Wc1 + c * 97;
        const float* tp = top + k * 97;
        float s = bc1[c];
        for (int d = 0; d < 97; d++) s = fmaf(tp[d], w[d], s);
        y1[c * 30 + k] = fmaxf(s, 0.f);
    }
    __syncthreads();

    // MaxPool1d(2,2)
    for (int o = t; o < 16 * 15; o += 128) {
        int c = o / 15, k = o - 15 * c;
        pmax[o] = fmaxf(y1[c * 30 + 2 * k], y1[c * 30 + 2 * k + 1]);
    }
    __syncthreads();

    // Conv1d(16,32,5) -> g_y2 (flatten index o*11+k)
    for (int o2 = t; o2 < 32 * 11; o2 += 128) {
        int o = o2 / 11, k = o2 - 11 * o;
        float s = bc2[o];
        for (int i = 0; i < 16; i++) {
            const float* wp = Wc2 + (o * 16 + i) * 5;
            const float* pp = pmax + i * 15 + k;
#pragma unroll
            for (int tt = 0; tt < 5; tt++) s = fmaf(pp[tt], wp[tt], s);
        }
        g_y2[g * 352 + o2] = fmaxf(s, 0.f);
    }
}

// ---- head part 2: [NG,352] @ Wl1 -> relu -> @ Wl2. GPB graphs per block. ----

#define GPB 10

__global__ void __launch_bounds__(128)
k_fc2(const float* __restrict__ Wl1, const float* __restrict__ bl1,
      const float* __restrict__ Wl2, const float* __restrict__ bl2,
      float* __restrict__ out) {
    __shared__ float4 sy[GPB * 88];      // GPB x 352 floats
    __shared__ float  sred[4][GPB];
    int t = threadIdx.x;
    int g0 = blockIdx.x * GPB;

    // stage y2 rows (coalesced float4)
    const float4* y4 = (const float4*)(g_y2 + g0 * 352);
    for (int i = t; i < GPB * 88; i += 128) sy[i] = y4[i];
    __syncthreads();

    float acc[GPB];
    float b = bl1[t];
#pragma unroll
    for (int g = 0; g < GPB; g++) acc[g] = b;

    for (int m4 = 0; m4 < 88; m4++) {
        float w0 = Wl1[(4 * m4 + 0) * 128 + t];
        float w1 = Wl1[(4 * m4 + 1) * 128 + t];
        float w2 = Wl1[(4 * m4 + 2) * 128 + t];
        float w3 = Wl1[(4 * m4 + 3) * 128 + t];
#pragma unroll
        for (int g = 0; g < GPB; g++) {
            float4 y = sy[g * 88 + m4];
            float a = acc[g];
            a = fmaf(y.x, w0, a);
            a = fmaf(y.y, w1, a);
            a = fmaf(y.z, w2, a);
            a = fmaf(y.w, w3, a);
            acc[g] = a;
        }
    }

    float wl2t = Wl2[t];
    int lane = t & 31, warp = t >> 5;
#pragma unroll
    for (int g = 0; g < GPB; g++) {
        float p = fmaxf(acc[g], 0.f) * wl2t;
#pragma unroll
        for (int off = 16; off; off >>= 1) p += __shfl_down_sync(0xffffffffu, p, off);
        if (lane == 0) sred[warp][g] = p;
    }
    __syncthreads();
    if (t < GPB)
        out[g0 + t] = sred[0][t] + sred[1][t] + sred[2][t] + sred[3][t] + bl2[0];
}

// ---------------------------------------------------------------------------

extern "C" void kernel_launch(void* const* d_in, const int* in_sizes, int n_in,
                              void* d_out, int out_size) {
    const int*   z    = (const int*)d_in[0];
    const int*   eidx = (const int*)d_in[1];
    const float* ew   = (const float*)d_in[3];
    const float* zemb = (const float*)d_in[4];
    const float* Wg1 = (const float*)d_in[5];
    const float* bg1 = (const float*)d_in[6];
    const float* Wg2 = (const float*)d_in[7];
    const float* bg2 = (const float*)d_in[8];
    const float* Wg3 = (const float*)d_in[9];
    const float* bg3 = (const float*)d_in[10];
    const float* Wg4 = (const float*)d_in[11];
    const float* bg4 = (const float*)d_in[12];
    const float* Wc1 = (const float*)d_in[13];
    const float* bc1 = (const float*)d_in[14];
    const float* Wc2 = (const float*)d_in[15];
    const float* bc2 = (const float*)d_in[16];
    const float* Wl1 = (const float*)d_in[17];
    const float* bl1 = (const float*)d_in[18];
    const float* Wl2 = (const float*)d_in[19];
    const float* bl2 = (const float*)d_in[20];
    float* out = (float*)d_out;

    const int n = in_sizes[0];          // 100000
    const int e = in_sizes[3];          // 1600000
    const int nz = in_sizes[4] / 32;    // 1000 (z_emb rows)
    const int* src = eidx;
    const int* dst = eidx + e;

    const int TB = 256;
    int gN   = (n + TB - 1) / TB;
    int gE   = (e + TB - 1) / TB;
    int gN8  = (n + 7) / 8;
    int gN32 = (n * 32 + TB - 1) / TB;

    float *xwA, *xwB, *h1, *h2;
    cudaGetSymbolAddress((void**)&xwA, g_xwA);
    cudaGetSymbolAddress((void**)&xwB, g_xwB);
    cudaGetSymbolAddress((void**)&h1, g_h1);
    cudaGetSymbolAddress((void**)&h2, g_h2);

    // build padded CSR + dinv
    k_zero<<<gN, TB>>>(n);
    k_fill<<<gE, TB>>>(src, dst, ew, e);
    k_degdinv<<<gN32, TB>>>(n);

    // z table + embedding gather
    k_zw<<<(nz + 7) / 8, TB>>>(zemb, Wg1, nz);
    k_emb_gather<<<gN32, TB>>>(z, n);

    // GCN stack (pre-scaled features)
    k_layer32<<<gN8, TB>>>(bg1, Wg2, h1, xwA, xwB, n);
    k_layer32<<<gN8, TB>>>(bg2, Wg3, h2, xwB, xwA, n);
    k_layer_last<<<gN32, TB>>>(bg3, Wg4, xwA, n);

    // head
    k_head1<<<NG, 128>>>(bg4, Wc1, bc1, Wc2, bc2);
    k_fc2<<<NG / GPB, 128>>>(Wl1, bl1, Wl2, bl2, out);
}

// round 8
// speedup vs baseline: 1.1547x; 1.1547x over previous
#include <cuda_runtime.h>
#include <math.h>

// ---------------------------------------------------------------------------
// DGCNN forward, CSR-gather with pre-scaled features, float2 pair layout.
//   xws[v] = (h@W) * dinv[v]  =>  gcn_out[d] = dinv[d]*(sum_e ew*xws[src] + xws[d])
// Adjacency stores (src*128 byte offset, raw ew); rows padded to multiple of 8.
// Wide layers: 2 nodes per warp, 16 lanes x float2 channels.
// ---------------------------------------------------------------------------

#define NN 100000
#define EE 1600000
#define NG 1000
#define SLOT 64   // padded CSR row stride (Poisson(16) tail beyond 64 ~1e-20)

__device__ int   g_cnt[NN];
__device__ float g_dinv[NN];
__device__ int2  g_adj[(size_t)NN * SLOT];   // (src*128, ew bits)
__device__ float g_zw[1000 * 32];            // z_emb @ Wg1 table
__device__ float g_xwA[NN * 32];             // pre-scaled features
__device__ float g_xwB[NN * 32];
__device__ float g_h1[NN * 32];
__device__ float g_h2[NN * 32];
__device__ float g_h3[NN * 32];
__device__ float g_xw4[NN];
__device__ float g_y2[NG * 352];

// ---- CSR build --------------------------------------------------------------

__global__ void k_zero(int n) {
    int i = blockIdx.x * blockDim.x + threadIdx.x;
    if (i < n) g_cnt[i] = 0;
}

__global__ void k_fill(const int* __restrict__ src, const int* __restrict__ dst,
                       const float* __restrict__ ew, int e) {
    int i = blockIdx.x * blockDim.x + threadIdx.x;
    if (i >= e) return;
    int d = dst[i];
    int pos = atomicAdd(&g_cnt[d], 1);
    if (pos < SLOT)
        g_adj[(size_t)d * SLOT + pos] = make_int2(src[i] << 7, __float_as_int(ew[i]));
}

// warp per node: deg = 1 + sum(row ew); dinv = rsqrt(deg); pad row to mult of 8.
__global__ void k_degdinv(int n) {
    int tid  = blockIdx.x * blockDim.x + threadIdx.x;
    int node = tid >> 5, lane = tid & 31;
    if (node >= n) return;
    int c = min(g_cnt[node], SLOT);
    int2* row = g_adj + (size_t)node * SLOT;
    float w = 0.f;
    if (lane < c)      w += __int_as_float(row[lane].y);
    if (lane + 32 < c) w += __int_as_float(row[lane + 32].y);
#pragma unroll
    for (int off = 16; off; off >>= 1) w += __shfl_xor_sync(0xffffffffu, w, off);
    int cpad = (c + 7) & ~7;
    if (c + lane < cpad) row[c + lane] = make_int2(0, 0);   // zero-wt dummy -> node 0
    if (lane == 0) {
        g_dinv[node] = rsqrtf(1.0f + w);
        g_cnt[node]  = cpad;
    }
}

// ---- z table: zw = z_emb @ Wg1 (1000 x 32) ---------------------------------

__global__ void k_zw(const float* __restrict__ z_emb, const float* __restrict__ W, int nz) {
    __shared__ float sW[1024];
    int tid = threadIdx.x;
    for (int i = tid; i < 1024; i += 256) sW[i] = W[i];
    __syncthreads();
    int warp = tid >> 5, lane = tid & 31;
    int row = blockIdx.x * 8 + warp;
    if (row >= nz) return;
    float h = z_emb[row * 32 + lane];
    float o = 0.f;
#pragma unroll
    for (int k = 0; k < 32; k++)
        o = fmaf(__shfl_sync(0xffffffffu, h, k), sW[k * 32 + lane], o);
    g_zw[row * 32 + lane] = o;
}

// xwA[node] = zw[z[node]] * dinv[node]  (pure gather, float2)
__global__ void k_emb_gather(const int* __restrict__ z, int n) {
    int i = blockIdx.x * blockDim.x + threadIdx.x;   // n*16 threads
    if (i >= n * 16) return;
    int node = i >> 4, p = i & 15;
    float2 zv = ((const float2*)g_zw)[z[node] * 16 + p];
    float dv = g_dinv[node];
    ((float2*)g_xwA)[i] = make_float2(zv.x * dv, zv.y * dv);
}

// ---- pair aggregation: 2 nodes/warp, 16 lanes x float2 ----------------------

__device__ __forceinline__ float2 agg_pair(const char* __restrict__ bp,  // xwIn + sl*8
                                           int node, int c) {
    float2 acc = *(const float2*)(bp + (node << 7));
    const int4* row4 = (const int4*)(g_adj + (size_t)node * SLOT);
    for (int j = 0; j < c; j += 8) {
        int4 m0 = row4[(j >> 1) + 0];
        int4 m1 = row4[(j >> 1) + 1];
        int4 m2 = row4[(j >> 1) + 2];
        int4 m3 = row4[(j >> 1) + 3];
        float2 v0 = *(const float2*)(bp + m0.x);
        float2 v1 = *(const float2*)(bp + m0.z);
        float2 v2 = *(const float2*)(bp + m1.x);
        float2 v3 = *(const float2*)(bp + m1.z);
        float2 v4 = *(const float2*)(bp + m2.x);
        float2 v5 = *(const float2*)(bp + m2.z);
        float2 v6 = *(const float2*)(bp + m3.x);
        float2 v7 = *(const float2*)(bp + m3.z);
        float w0 = __int_as_float(m0.y), w1 = __int_as_float(m0.w);
        float w2 = __int_as_float(m1.y), w3 = __int_as_float(m1.w);
        float w4 = __int_as_float(m2.y), w5 = __int_as_float(m2.w);
        float w6 = __int_as_float(m3.y), w7 = __int_as_float(m3.w);
        acc.x = fmaf(w0, v0.x, acc.x); acc.y = fmaf(w0, v0.y, acc.y);
        acc.x = fmaf(w1, v1.x, acc.x); acc.y = fmaf(w1, v1.y, acc.y);
        acc.x = fmaf(w2, v2.x, acc.x); acc.y = fmaf(w2, v2.y, acc.y);
        acc.x = fmaf(w3, v3.x, acc.x); acc.y = fmaf(w3, v3.y, acc.y);
        acc.x = fmaf(w4, v4.x, acc.x); acc.y = fmaf(w4, v4.y, acc.y);
        acc.x = fmaf(w5, v5.x, acc.x); acc.y = fmaf(w5, v5.y, acc.y);
        acc.x = fmaf(w6, v6.x, acc.x); acc.y = fmaf(w6, v6.y, acc.y);
        acc.x = fmaf(w7, v7.x, acc.x); acc.y = fmaf(w7, v7.y, acc.y);
    }
    return acc;
}

// ---- fused GCN layer (pair layout): agg -> tanh -> h -> GEMM -> prescale ----

__global__ void __launch_bounds__(256)
k_layer32(const float* __restrict__ bprev, const float* __restrict__ W,
          float* __restrict__ hOut, const float* __restrict__ xwIn,
          float* __restrict__ xwOut, int n) {
    __shared__ float2 sW2[512];          // sW2[k*16+p] = (W[k][2p], W[k][2p+1])
    __shared__ float  sH[8][64];         // [warp][half*32 + ch]
    int tid = threadIdx.x;
    {
        const float2* W2 = (const float2*)W;
        for (int i = tid; i < 512; i += 256) sW2[i] = W2[i];
    }
    __syncthreads();
    int warp = tid >> 5, lane = tid & 31, half = lane >> 4, sl = lane & 15;
    int node = blockIdx.x * 16 + warp * 2 + half;   // n divisible by 16
    float dv = g_dinv[node];
    int   c  = g_cnt[node];
    const char* bp = (const char*)xwIn + sl * 8;
    float2 acc = agg_pair(bp, node, c);
    float2 bb = ((const float2*)bprev)[sl];
    float h0 = tanhf(fmaf(acc.x, dv, bb.x));
    float h1 = tanhf(fmaf(acc.y, dv, bb.y));
    *(float2*)((char*)hOut + (node << 7) + sl * 8) = make_float2(h0, h1);
    float* hh = &sH[warp][half * 32];
    hh[2 * sl] = h0; hh[2 * sl + 1] = h1;
    __syncwarp();
    float ox0 = 0.f, oy0 = 0.f, ox1 = 0.f, oy1 = 0.f;
#pragma unroll
    for (int k = 0; k < 32; k += 2) {
        float hk0 = hh[k], hk1 = hh[k + 1];
        float2 w0 = sW2[(k + 0) * 16 + sl];
        float2 w1 = sW2[(k + 1) * 16 + sl];
        ox0 = fmaf(hk0, w0.x, ox0); oy0 = fmaf(hk0, w0.y, oy0);
        ox1 = fmaf(hk1, w1.x, ox1); oy1 = fmaf(hk1, w1.y, oy1);
    }
    *(float2*)((char*)xwOut + (node << 7) + sl * 8) =
        make_float2((ox0 + ox1) * dv, (oy0 + oy1) * dv);
}

// last GCN layer (pair layout): project to scalar via Wg4
__global__ void __launch_bounds__(256)
k_layer_last(const float* __restrict__ bg3, const float* __restrict__ Wg4,
             const float* __restrict__ xwIn, int n) {
    int tid = blockIdx.x * blockDim.x + threadIdx.x;
    int lane = tid & 31, half = lane >> 4, sl = lane & 15;
    int node = ((tid >> 5) << 1) + half;            // 2 nodes per warp
    if (node >= n) return;
    float dv = g_dinv[node];
    int   c  = g_cnt[node];
    const char* bp = (const char*)xwIn + sl * 8;
    float2 acc = agg_pair(bp, node, c);
    float2 bb = ((const float2*)bg3)[sl];
    float h0 = tanhf(fmaf(acc.x, dv, bb.x));
    float h1 = tanhf(fmaf(acc.y, dv, bb.y));
    *(float2*)((char*)g_h3 + (node << 7) + sl * 8) = make_float2(h0, h1);
    float2 w4 = ((const float2*)Wg4)[sl];
    float p = h0 * w4.x + h1 * w4.y;
#pragma unroll
    for (int off = 8; off; off >>= 1) p += __shfl_down_sync(0xffffffffu, p, off, 16);
    if (sl == 0) g_xw4[node] = p * dv;
}

// ---- head part 1: scalar agg + sort-pool + conv1 + pool + conv2 -> g_y2 -----

__global__ void __launch_bounds__(128)
k_head1(const float* __restrict__ bg4,
        const float* __restrict__ Wc1, const float* __restrict__ bc1,
        const float* __restrict__ Wc2, const float* __restrict__ bc2) {
    __shared__ float v[100];
    __shared__ int   topidx[30];
    __shared__ float top[30 * 97];
    __shared__ float y1[16 * 30];
    __shared__ float pmax[16 * 15];

    int g = blockIdx.x;
    int t = threadIdx.x;
    float b4 = bg4[0];
    const char* x4b = (const char*)g_xw4;

    if (t < 100) {
        int node = g * 100 + t;
        float acc = g_xw4[node];
        int c = g_cnt[node];
        const int4* row4 = (const int4*)(g_adj + (size_t)node * SLOT);
        for (int j = 0; j < c; j += 8) {
            int4 m0 = row4[(j >> 1) + 0];
            int4 m1 = row4[(j >> 1) + 1];
            int4 m2 = row4[(j >> 1) + 2];
            int4 m3 = row4[(j >> 1) + 3];
            float v0 = *(const float*)(x4b + (m0.x >> 5));
            float v1 = *(const float*)(x4b + (m0.z >> 5));
            float v2 = *(const float*)(x4b + (m1.x >> 5));
            float v3 = *(const float*)(x4b + (m1.z >> 5));
            float v4 = *(const float*)(x4b + (m2.x >> 5));
            float v5 = *(const float*)(x4b + (m2.z >> 5));
            float v6 = *(const float*)(x4b + (m3.x >> 5));
            float v7 = *(const float*)(x4b + (m3.z >> 5));
            acc = fmaf(__int_as_float(m0.y), v0, acc);
            acc = fmaf(__int_as_float(m0.w), v1, acc);
            acc = fmaf(__int_as_float(m1.y), v2, acc);
            acc = fmaf(__int_as_float(m1.w), v3, acc);
            acc = fmaf(__int_as_float(m2.y), v4, acc);
            acc = fmaf(__int_as_float(m2.w), v5, acc);
            acc = fmaf(__int_as_float(m3.y), v6, acc);
            acc = fmaf(__int_as_float(m3.w), v7, acc);
        }
        v[t] = tanhf(fmaf(acc, g_dinv[node], b4));
    }
    __syncthreads();

    // stable descending rank select (ties -> lower index first)
    if (t < 100) {
        float vt = v[t];
        int r = 0;
#pragma unroll 4
        for (int m = 0; m < 100; m++) {
            float vm = v[m];
            r += (vm > vt) || (vm == vt && m < t);
        }
        if (r < 30) topidx[r] = t;
    }
    __syncthreads();

    // gather top-30 latent rows (h1|h2|h3|v) into [30][97]
    for (int e = t; e < 30 * 97; e += 128) {
        int r = e / 97, d = e - 97 * r;
        int nd = g * 100 + topidx[r];
        float val;
        if (d < 32)       val = g_h1[nd * 32 + d];
        else if (d < 64)  val = g_h2[nd * 32 + d - 32];
        else if (d < 96)  val = g_h3[nd * 32 + d - 64];
        else              val = v[topidx[r]];
        top[e] = val;
    }
    __syncthreads();

    // Conv1d(1,16,97,stride 97)
    for (int o = t; o < 16 * 30; o += 128) {
        int c = o / 30, k = o - 30 * c;
        const float* w  = Wc1 + c * 97;
        const float* tp = top + k * 97;
        float s = bc1[c];
        for (int d = 0; d < 97; d++) s = fmaf(tp[d], w[d], s);
        y1[c * 30 + k] = fmaxf(s, 0.f);
    }
    __syncthreads();

    // MaxPool1d(2,2)
    for (int o = t; o < 16 * 15; o += 128) {
        int c = o / 15, k = o - 15 * c;
        pmax[o] = fmaxf(y1[c * 30 + 2 * k], y1[c * 30 + 2 * k + 1]);
    }
    __syncthreads();

    // Conv1d(16,32,5) -> g_y2
    for (int o2 = t; o2 < 32 * 11; o2 += 128) {
        int o = o2 / 11, k = o2 - 11 * o;
        float s = bc2[o];
        for (int i = 0; i < 16; i++) {
            const float* wp = Wc2 + (o * 16 + i) * 5;
            const float* pp = pmax + i * 15 + k;
#pragma unroll
            for (int tt = 0; tt < 5; tt++) s = fmaf(pp[tt], wp[tt], s);
        }
        g_y2[g * 352 + o2] = fmaxf(s, 0.f);
    }
}

// ---- head part 2: [NG,352] @ Wl1 -> relu -> @ Wl2 ---------------------------

#define GPB 10

__global__ void __launch_bounds__(128)
k_fc2(const float* __restrict__ Wl1, const float* __restrict__ bl1,
      const float* __restrict__ Wl2, const float* __restrict__ bl2,
      float* __restrict__ out) {
    __shared__ float4 sy[GPB * 88];
    __shared__ float  sred[4][GPB];
    int t = threadIdx.x;
    int g0 = blockIdx.x * GPB;

    const float4* y4 = (const float4*)(g_y2 + g0 * 352);
    for (int i = t; i < GPB * 88; i += 128) sy[i] = y4[i];
    __syncthreads();

    float acc[GPB];
    float b = bl1[t];
#pragma unroll
    for (int g = 0; g < GPB; g++) acc[g] = b;

    for (int m4 = 0; m4 < 88; m4++) {
        float w0 = Wl1[(4 * m4 + 0) * 128 + t];
        float w1 = Wl1[(4 * m4 + 1) * 128 + t];
        float w2 = Wl1[(4 * m4 + 2) * 128 + t];
        float w3 = Wl1[(4 * m4 + 3) * 128 + t];
#pragma unroll
        for (int g = 0; g < GPB; g++) {
            float4 y = sy[g * 88 + m4];
            float a = acc[g];
            a = fmaf(y.x, w0, a);
            a = fmaf(y.y, w1, a);
            a = fmaf(y.z, w2, a);
            a = fmaf(y.w, w3, a);
            acc[g] = a;
        }
    }

    float wl2t = Wl2[t];
    int lane = t & 31, warp = t >> 5;
#pragma unroll
    for (int g = 0; g < GPB; g++) {
        float p = fmaxf(acc[g], 0.f) * wl2t;
#pragma unroll
        for (int off = 16; off; off >>= 1) p += __shfl_down_sync(0xffffffffu, p, off);
        if (lane == 0) sred[warp][g] = p;
    }
    __syncthreads();
    if (t < GPB)
        out[g0 + t] = sred[0][t] + sred[1][t] + sred[2][t] + sred[3][t] + bl2[0];
}

// ---------------------------------------------------------------------------

extern "C" void kernel_launch(void* const* d_in, const int* in_sizes, int n_in,
                              void* d_out, int out_size) {
    const int*   z    = (const int*)d_in[0];
    const int*   eidx = (const int*)d_in[1];
    const float* ew   = (const float*)d_in[3];
    const float* zemb = (const float*)d_in[4];
    const float* Wg1 = (const float*)d_in[5];
    const float* bg1 = (const float*)d_in[6];
    const float* Wg2 = (const float*)d_in[7];
    const float* bg2 = (const float*)d_in[8];
    const float* Wg3 = (const float*)d_in[9];
    const float* bg3 = (const float*)d_in[10];
    const float* Wg4 = (const float*)d_in[11];
    const float* bg4 = (const float*)d_in[12];
    const float* Wc1 = (const float*)d_in[13];
    const float* bc1 = (const float*)d_in[14];
    const float* Wc2 = (const float*)d_in[15];
    const float* bc2 = (const float*)d_in[16];
    const float* Wl1 = (const float*)d_in[17];
    const float* bl1 = (const float*)d_in[18];
    const float* Wl2 = (const float*)d_in[19];
    const float* bl2 = (const float*)d_in[20];
    float* out = (float*)d_out;

    const int n = in_sizes[0];          // 100000
    const int e = in_sizes[3];          // 1600000
    const int nz = in_sizes[4] / 32;    // 1000
    const int* src = eidx;
    const int* dst = eidx + e;

    const int TB = 256;
    int gN   = (n + TB - 1) / TB;
    int gE   = (e + TB - 1) / TB;
    int gN16 = (n + 15) / 16;           // pair layout: 16 nodes / 256-thr block
    int gN32 = (n * 32 + TB - 1) / TB;
    int gNP  = (n * 16 + TB - 1) / TB;  // pair-flat: 2 nodes per warp

    float *xwA, *xwB, *h1, *h2;
    cudaGetSymbolAddress((void**)&xwA, g_xwA);
    cudaGetSymbolAddress((void**)&xwB, g_xwB);
    cudaGetSymbolAddress((void**)&h1, g_h1);
    cudaGetSymbolAddress((void**)&h2, g_h2);

    // build padded CSR + dinv
    k_zero<<<gN, TB>>>(n);
    k_fill<<<gE, TB>>>(src, dst, ew, e);
    k_degdinv<<<gN32, TB>>>(n);

    // z table + embedding gather
    k_zw<<<(nz + 7) / 8, TB>>>(zemb, Wg1, nz);
    k_emb_gather<<<gNP, TB>>>(z, n);

    // GCN stack (pair layout)
    k_layer32<<<gN16, TB>>>(bg1, Wg2, h1, xwA, xwB, n);
    k_layer32<<<gN16, TB>>>(bg2, Wg3, h2, xwB, xwA, n);
    k_layer_last<<<gNP, TB>>>(bg3, Wg4, xwA, n);

    // head
    k_head1<<<NG, 128>>>(bg4, Wc1, bc1, Wc2, bc2);
    k_fc2<<<NG / GPB, 128>>>(Wl1, bl1, Wl2, bl2, out);
}

// round 10
// speedup vs baseline: 1.2612x; 1.0923x over previous
#include <cuda_runtime.h>
#include <math.h>

// ---------------------------------------------------------------------------
// DGCNN forward, CSR-gather with pre-scaled features, float4 quad layout.
//   xws[v] = (h@W) * dinv[v]  =>  gcn_out[d] = dinv[d]*(sum_e ew*xws[src] + xws[d])
// Adjacency stores (src*128 byte offset, raw ew); rows padded to multiple of 8.
// Wide layers: 4 nodes per warp, 8 lanes x float4 channels.
// ---------------------------------------------------------------------------

#define NN 100000
#define EE 1600000
#define NG 1000
#define SLOT 64   // padded CSR row stride (Poisson(16) tail beyond 64 ~1e-20)

__device__ int   g_cnt[NN];
__device__ float g_dinv[NN];
__device__ int2  g_adj[(size_t)NN * SLOT];   // (src*128, ew bits)
__device__ float g_zw[1000 * 32];            // z_emb @ Wg1 table
__device__ float g_xwA[NN * 32];             // pre-scaled features
__device__ float g_xwB[NN * 32];
__device__ float g_h1[NN * 32];
__device__ float g_h2[NN * 32];
__device__ float g_h3[NN * 32];
__device__ float g_xw4[NN];
__device__ float g_y2[NG * 352];

// ---- CSR build --------------------------------------------------------------

__global__ void k_zero(int n) {
    int i = blockIdx.x * blockDim.x + threadIdx.x;
    if (i < n) g_cnt[i] = 0;
}

// blocks [0,nFill): edge fill; blocks [nFill, ...): zw = z_emb @ Wg1 table
__global__ void k_fill_zw(const int* __restrict__ src, const int* __restrict__ dst,
                          const float* __restrict__ ew, int e, int nFill,
                          const float* __restrict__ z_emb, const float* __restrict__ W,
                          int nz) {
    if ((int)blockIdx.x < nFill) {
        int i = blockIdx.x * blockDim.x + threadIdx.x;
        if (i >= e) return;
        int d = dst[i];
        int pos = atomicAdd(&g_cnt[d], 1);
        if (pos < SLOT)
            g_adj[(size_t)d * SLOT + pos] = make_int2(src[i] << 7, __float_as_int(ew[i]));
    } else {
        __shared__ float sW[1024];
        int tid = threadIdx.x;
        for (int i = tid; i < 1024; i += 256) sW[i] = W[i];
        __syncthreads();
        int warp = tid >> 5, lane = tid & 31;
        int row = ((int)blockIdx.x - nFill) * 8 + warp;
        if (row >= nz) return;
        float h = z_emb[row * 32 + lane];
        float o = 0.f;
#pragma unroll
        for (int k = 0; k < 32; k++)
            o = fmaf(__shfl_sync(0xffffffffu, h, k), sW[k * 32 + lane], o);
        g_zw[row * 32 + lane] = o;
    }
}

// warp per node: deg -> dinv, pad row to mult of 8, AND write xwA = zw[z]*dinv
__global__ void k_degdinv_emb(const int* __restrict__ z, int n) {
    int tid  = blockIdx.x * blockDim.x + threadIdx.x;
    int node = tid >> 5, lane = tid & 31;
    if (node >= n) return;
    int c = min(g_cnt[node], SLOT);
    int2* row = g_adj + (size_t)node * SLOT;
    float w = 0.f;
    if (lane < c)      w += __int_as_float(row[lane].y);
    if (lane + 32 < c) w += __int_as_float(row[lane + 32].y);
#pragma unroll
    for (int off = 16; off; off >>= 1) w += __shfl_xor_sync(0xffffffffu, w, off);
    float dv = rsqrtf(1.0f + w);                            // all lanes
    int cpad = (c + 7) & ~7;
    if (c + lane < cpad) row[c + lane] = make_int2(0, 0);   // zero-wt dummy -> node 0
    if (lane == 0) {
        g_dinv[node] = dv;
        g_cnt[node]  = cpad;
    }
    int zi = z[node];                                       // broadcast load
    g_xwA[node * 32 + lane] = g_zw[zi * 32 + lane] * dv;
}

// ---- quad aggregation: 4 nodes/warp, 8 lanes x float4 -----------------------

__device__ __forceinline__ float4 agg_quad(const char* __restrict__ bp,  // xwIn + sl*16
                                           int node, int c) {
    float4 acc = *(const float4*)(bp + (node << 7));
    const int4* row4 = (const int4*)(g_adj + (size_t)node * SLOT);
    for (int j = 0; j < c; j += 8) {
        int4 m0 = row4[(j >> 1) + 0];
        int4 m1 = row4[(j >> 1) + 1];
        int4 m2 = row4[(j >> 1) + 2];
        int4 m3 = row4[(j >> 1) + 3];
        float4 v0 = *(const float4*)(bp + m0.x);
        float4 v1 = *(const float4*)(bp + m0.z);
        float4 v2 = *(const float4*)(bp + m1.x);
        float4 v3 = *(const float4*)(bp + m1.z);
        float4 v4 = *(const float4*)(bp + m2.x);
        float4 v5 = *(const float4*)(bp + m2.z);
        float4 v6 = *(const float4*)(bp + m3.x);
        float4 v7 = *(const float4*)(bp + m3.z);
        float w0 = __int_as_float(m0.y), w1 = __int_as_float(m0.w);
        float w2 = __int_as_float(m1.y), w3 = __int_as_float(m1.w);
        float w4 = __int_as_float(m2.y), w5 = __int_as_float(m2.w);
        float w6 = __int_as_float(m3.y), w7 = __int_as_float(m3.w);
        acc.x = fmaf(w0, v0.x, acc.x); acc.y = fmaf(w0, v0.y, acc.y);
        acc.z = fmaf(w0, v0.z, acc.z); acc.w = fmaf(w0, v0.w, acc.w);
        acc.x = fmaf(w1, v1.x, acc.x); acc.y = fmaf(w1, v1.y, acc.y);
        acc.z = fmaf(w1, v1.z, acc.z); acc.w = fmaf(w1, v1.w, acc.w);
        acc.x = fmaf(w2, v2.x, acc.x); acc.y = fmaf(w2, v2.y, acc.y);
        acc.z = fmaf(w2, v2.z, acc.z); acc.w = fmaf(w2, v2.w, acc.w);
        acc.x = fmaf(w3, v3.x, acc.x); acc.y = fmaf(w3, v3.y, acc.y);
        acc.z = fmaf(w3, v3.z, acc.z); acc.w = fmaf(w3, v3.w, acc.w);
        acc.x = fmaf(w4, v4.x, acc.x); acc.y = fmaf(w4, v4.y, acc.y);
        acc.z = fmaf(w4, v4.z, acc.z); acc.w = fmaf(w4, v4.w, acc.w);
        acc.x = fmaf(w5, v5.x, acc.x); acc.y = fmaf(w5, v5.y, acc.y);
        acc.z = fmaf(w5, v5.z, acc.z); acc.w = fmaf(w5, v5.w, acc.w);
        acc.x = fmaf(w6, v6.x, acc.x); acc.y = fmaf(w6, v6.y, acc.y);
        acc.z = fmaf(w6, v6.z, acc.z); acc.w = fmaf(w6, v6.w, acc.w);
        acc.x = fmaf(w7, v7.x, acc.x); acc.y = fmaf(w7, v7.y, acc.y);
        acc.z = fmaf(w7, v7.z, acc.z); acc.w = fmaf(w7, v7.w, acc.w);
    }
    return acc;
}

// ---- fused GCN layer (quad layout): agg -> tanh -> h -> GEMM -> prescale ----

__global__ void __launch_bounds__(256)
k_layer32(const float* __restrict__ bprev, const float* __restrict__ W,
          float* __restrict__ hOut, const float* __restrict__ xwIn,
          float* __restrict__ xwOut, int n) {
    __shared__ float4 sW4[256];          // sW4[k*8+sl] = W[k][4sl..4sl+3]
    __shared__ float  sH[8][132];        // [warp][q*33 + k], +33 stride kills conflicts
    int tid = threadIdx.x;
    {
        const float4* W4 = (const float4*)W;
        sW4[tid] = W4[tid];
    }
    __syncthreads();
    int warp = tid >> 5, lane = tid & 31, q = lane >> 3, sl = lane & 7;
    int node = blockIdx.x * 32 + warp * 4 + q;      // n divisible by 32
    if (node >= n) return;
    float dv = g_dinv[node];
    int   c  = g_cnt[node];
    const char* bp = (const char*)xwIn + sl * 16;
    float4 acc = agg_quad(bp, node, c);
    float4 bb = ((const float4*)bprev)[sl];
    float4 h;
    h.x = tanhf(fmaf(acc.x, dv, bb.x));
    h.y = tanhf(fmaf(acc.y, dv, bb.y));
    h.z = tanhf(fmaf(acc.z, dv, bb.z));
    h.w = tanhf(fmaf(acc.w, dv, bb.w));
    *(float4*)((char*)hOut + (node << 7) + sl * 16) = h;
    float* hh = &sH[warp][q * 33];
    hh[4 * sl + 0] = h.x; hh[4 * sl + 1] = h.y;
    hh[4 * sl + 2] = h.z; hh[4 * sl + 3] = h.w;
    __syncwarp();
    float4 o = make_float4(0.f, 0.f, 0.f, 0.f);
#pragma unroll
    for (int k = 0; k < 32; k++) {
        float hk = hh[k];
        float4 w = sW4[k * 8 + sl];
        o.x = fmaf(hk, w.x, o.x); o.y = fmaf(hk, w.y, o.y);
        o.z = fmaf(hk, w.z, o.z); o.w = fmaf(hk, w.w, o.w);
    }
    *(float4*)((char*)xwOut + (node << 7) + sl * 16) =
        make_float4(o.x * dv, o.y * dv, o.z * dv, o.w * dv);
}

// last GCN layer (quad layout): project to scalar via Wg4
__global__ void __launch_bounds__(256)
k_layer_last(const float* __restrict__ bg3, const float* __restrict__ Wg4,
             const float* __restrict__ xwIn, int n) {
    int i = blockIdx.x * blockDim.x + threadIdx.x;   // n*8 threads
    int node = i >> 3, sl = i & 7;
    if (node >= n) return;
    float dv = g_dinv[node];
    int   c  = g_cnt[node];
    const char* bp = (const char*)xwIn + sl * 16;
    float4 acc = agg_quad(bp, node, c);
    float4 bb = ((const float4*)bg3)[sl];
    float4 h;
    h.x = tanhf(fmaf(acc.x, dv, bb.x));
    h.y = tanhf(fmaf(acc.y, dv, bb.y));
    h.z = tanhf(fmaf(acc.z, dv, bb.z));
    h.w = tanhf(fmaf(acc.w, dv, bb.w));
    *(float4*)((char*)g_h3 + (node << 7) + sl * 16) = h;
    float4 w4 = ((const float4*)Wg4)[sl];
    float p = h.x * w4.x + h.y * w4.y + h.z * w4.z + h.w * w4.w;
#pragma unroll
    for (int off = 4; off; off >>= 1) p += __shfl_down_sync(0xffffffffu, p, off, 8);
    if (sl == 0) g_xw4[node] = p * dv;
}

// ---- head part 1: scalar agg + sort-pool + conv1 + pool + conv2 -> g_y2 -----

__global__ void __launch_bounds__(128)
k_head1(const float* __restrict__ bg4,
        const float* __restrict__ Wc1, const float* __restrict__ bc1,
        const float* __restrict__ Wc2, const float* __restrict__ bc2) {
    __shared__ float v[100];
    __shared__ int   topidx[30];
    __shared__ float top[30 * 97];
    __shared__ float y1[16 * 30];
    __shared__ float pmax[16 * 15];

    int g = blockIdx.x;
    int t = threadIdx.x;
    float b4 = bg4[0];
    const char* x4b = (const char*)g_xw4;

    if (t < 100) {
        int node = g * 100 + t;
        float acc = g_xw4[node];
        int c = g_cnt[node];
        const int4* row4 = (const int4*)(g_adj + (size_t)node * SLOT);
        for (int j = 0; j < c; j += 8) {
            int4 m0 = row4[(j >> 1) + 0];
            int4 m1 = row4[(j >> 1) + 1];
            int4 m2 = row4[(j >> 1) + 2];
            int4 m3 = row4[(j >> 1) + 3];
            float v0 = *(const float*)(x4b + (m0.x >> 5));
            float v1 = *(const float*)(x4b + (m0.z >> 5));
            float v2 = *(const float*)(x4b + (m1.x >> 5));
            float v3 = *(const float*)(x4b + (m1.z >> 5));
            float v4 = *(const float*)(x4b + (m2.x >> 5));
            float v5 = *(const float*)(x4b + (m2.z >> 5));
            float v6 = *(const float*)(x4b + (m3.x >> 5));
            float v7 = *(const float*)(x4b + (m3.z >> 5));
            acc = fmaf(__int_as_float(m0.y), v0, acc);
            acc = fmaf(__int_as_float(m0.w), v1, acc);
            acc = fmaf(__int_as_float(m1.y), v2, acc);
            acc = fmaf(__int_as_float(m1.w), v3, acc);
            acc = fmaf(__int_as_float(m2.y), v4, acc);
            acc = fmaf(__int_as_float(m2.w), v5, acc);
            acc = fmaf(__int_as_float(m3.y), v6, acc);
            acc = fmaf(__int_as_float(m3.w), v7, acc);
        }
        v[t] = tanhf(fmaf(acc, g_dinv[node], b4));
    }
    __syncthreads();

    // stable descending rank select (ties -> lower index first)
    if (t < 100) {
        float vt = v[t];
        int r = 0;
#pragma unroll 4
        for (int m = 0; m < 100; m++) {
            float vm = v[m];
            r += (vm > vt) || (vm == vt && m < t);
        }
        if (r < 30) topidx[r] = t;
    }
    __syncthreads();

    // gather top-30 latent rows (h1|h2|h3|v) into [30][97]
    for (int e = t; e < 30 * 97; e += 128) {
        int r = e / 97, d = e - 97 * r;
        int nd = g * 100 + topidx[r];
        float val;
        if (d < 32)       val = g_h1[nd * 32 + d];
        else if (d < 64)  val = g_h2[nd * 32 + d - 32];
        else if (d < 96)  val = g_h3[nd * 32 + d - 64];
        else              val = v[topidx[r]];
        top[e] = val;
    }
    __syncthreads();

    // Conv1d(1,16,97,stride 97)
    for (int o = t; o < 16 * 30; o += 128) {
        int c = o / 30, k = o - 30 * c;
        const float* w  = Wc1 + c * 97;
        const float* tp = top + k * 97;
        float s = bc1[c];
        for (int d = 0; d < 97; d++) s = fmaf(tp[d], w[d], s);
        y1[c * 30 + k] = fmaxf(s, 0.f);
    }
    __syncthreads();

    // MaxPool1d(2,2)
    for (int o = t; o < 16 * 15; o += 128) {
        int c = o / 15, k = o - 15 * c;
        pmax[o] = fmaxf(y1[c * 30 + 2 * k], y1[c * 30 + 2 * k + 1]);
    }
    __syncthreads();

    // Conv1d(16,32,5) -> g_y2
    for (int o2 = t; o2 < 32 * 11; o2 += 128) {
        int o = o2 / 11, k = o2 - 11 * o;
        float s = bc2[o];
        for (int i = 0; i < 16; i++) {
            const float* wp = Wc2 + (o * 16 + i) * 5;
            const float* pp = pmax + i * 15 + k;
#pragma unroll
            for (int tt = 0; tt < 5; tt++) s = fmaf(pp[tt], wp[tt], s);
        }
        g_y2[g * 352 + o2] = fmaxf(s, 0.f);
    }
}

// ---- head part 2: [NG,352] @ Wl1 -> relu -> @ Wl2 ---------------------------

#define GPB 10

__global__ void __launch_bounds__(128)
k_fc2(const float* __restrict__ Wl1, const float* __restrict__ bl1,
      const float* __restrict__ Wl2, const float* __restrict__ bl2,
      float* __restrict__ out) {
    __shared__ float4 sy[GPB * 88];
    __shared__ float  sred[4][GPB];
    int t = threadIdx.x;
    int g0 = blockIdx.x * GPB;

    const float4* y4 = (const float4*)(g_y2 + g0 * 352);
    for (int i = t; i < GPB * 88; i += 128) sy[i] = y4[i];
    __syncthreads();

    float acc[GPB];
    float b = bl1[t];
#pragma unroll
    for (int g = 0; g < GPB; g++) acc[g] = b;

    for (int m4 = 0; m4 < 88; m4++) {
        float w0 = Wl1[(4 * m4 + 0) * 128 + t];
        float w1 = Wl1[(4 * m4 + 1) * 128 + t];
        float w2 = Wl1[(4 * m4 + 2) * 128 + t];
        float w3 = Wl1[(4 * m4 + 3) * 128 + t];
#pragma unroll
        for (int g = 0; g < GPB; g++) {
            float4 y = sy[g * 88 + m4];
            float a = acc[g];
            a = fmaf(y.x, w0, a);
            a = fmaf(y.y, w1, a);
            a = fmaf(y.z, w2, a);
            a = fmaf(y.w, w3, a);
            acc[g] = a;
        }
    }

    float wl2t = Wl2[t];
    int lane = t & 31, warp = t >> 5;
#pragma unroll
    for (int g = 0; g < GPB; g++) {
        float p = fmaxf(acc[g], 0.f) * wl2t;
#pragma unroll
        for (int off = 16; off; off >>= 1) p += __shfl_down_sync(0xffffffffu, p, off);
        if (lane == 0) sred[warp][g] = p;
    }
    __syncthreads();
    if (t < GPB)
        out[g0 + t] = sred[0][t] + sred[1][t] + sred[2][t] + sred[3][t] + bl2[0];
}

// ---------------------------------------------------------------------------

extern "C" void kernel_launch(void* const* d_in, const int* in_sizes, int n_in,
                              void* d_out, int out_size) {
    const int*   z    = (const int*)d_in[0];
    const int*   eidx = (const int*)d_in[1];
    const float* ew   = (const float*)d_in[3];
    const float* zemb = (const float*)d_in[4];
    const float* Wg1 = (const float*)d_in[5];
    const float* bg1 = (const float*)d_in[6];
    const float* Wg2 = (const float*)d_in[7];
    const float* bg2 = (const float*)d_in[8];
    const float* Wg3 = (const float*)d_in[9];
    const float* bg3 = (const float*)d_in[10];
    const float* Wg4 = (const float*)d_in[11];
    const float* bg4 = (const float*)d_in[12];
    const float* Wc1 = (const float*)d_in[13];
    const float* bc1 = (const float*)d_in[14];
    const float* Wc2 = (const float*)d_in[15];
    const float* bc2 = (const float*)d_in[16];
    const float* Wl1 = (const float*)d_in[17];
    const float* bl1 = (const float*)d_in[18];
    const float* Wl2 = (const float*)d_in[19];
    const float* bl2 = (const float*)d_in[20];
    float* out = (float*)d_out;

    const int n = in_sizes[0];          // 100000
    const int e = in_sizes[3];          // 1600000
    const int nz = in_sizes[4] / 32;    // 1000
    const int* src = eidx;
    const int* dst = eidx + e;

    const int TB = 256;
    int gN    = (n + TB - 1) / TB;
    int gE    = (e + TB - 1) / TB;
    int gZW   = (nz + 7) / 8;
    int gN32b = (n + 31) / 32;          // quad layout: 32 nodes / 256-thr block
    int gN32  = (n * 32 + TB - 1) / TB; // warp per node
    int gNQ   = (n * 8 + TB - 1) / TB;  // quad-flat: 4 nodes per warp

    float *xwA, *xwB, *h1, *h2;
    cudaGetSymbolAddress((void**)&xwA, g_xwA);
    cudaGetSymbolAddress((void**)&xwB, g_xwB);
    cudaGetSymbolAddress((void**)&h1, g_h1);
    cudaGetSymbolAddress((void**)&h2, g_h2);

    // build padded CSR (+ zw table in spare blocks), then dinv + emb gather
    k_zero<<<gN, TB>>>(n);
    k_fill_zw<<<gE + gZW, TB>>>(src, dst, ew, e, gE, zemb, Wg1, nz);
    k_degdinv_emb<<<gN32, TB>>>(z, n);

    // GCN stack (quad layout)
    k_layer32<<<gN32b, TB>>>(bg1, Wg2, h1, xwA, xwB, n);
    k_layer32<<<gN32b, TB>>>(bg2, Wg3, h2, xwB, xwA, n);
    k_layer_last<<<gNQ, TB>>>(bg3, Wg4, xwA, n);

    // head
    k_head1<<<NG, 128>>>(bg4, Wc1, bc1, Wc2, bc2);
    k_fc2<<<NG / GPB, 128>>>(Wl1, bl1, Wl2, bl2, out);
}